// round 4
// baseline (speedup 1.0000x reference)
#include <cuda_runtime.h>
#include <cstdint>

#define NB 8
#define NPTS 32768
#define NC 128
#define NK 1024
#define CLUSTER 8
#define PTS_PER_CTA (NPTS / CLUSTER)     // 4096
#define NTHREADS 1024
#define PPT (PTS_PER_CTA / NTHREADS)     // 4

// sampled indices scratch (device global: no allocation allowed)
__device__ int g_idx[NB * NK];

struct SmemLayout {
    float4   coords[PTS_PER_CTA];      // 64 KB — winner coord lookup
    uint2    warp_vi[32];              // per-warp (valbits, idx)
    uint32_t cand[2][CLUSTER][8];      // double-buffered 32B candidate slots
    unsigned long long full[2];        // mbarriers (count = CLUSTER each)
};

__device__ __forceinline__ uint32_t smem_u32(const void* p) {
    uint32_t a;
    asm("{ .reg .u64 t; cvta.to.shared.u64 t, %1; cvt.u32.u64 %0, t; }"
        : "=r"(a) : "l"(p));
    return a;
}

__device__ __forceinline__ uint32_t mapa_rank(uint32_t laddr, uint32_t rank) {
    uint32_t r;
    asm("mapa.shared::cluster.u32 %0, %1, %2;" : "=r"(r) : "r"(laddr), "r"(rank));
    return r;
}

__device__ __forceinline__ void cluster_barrier() {
    asm volatile("barrier.cluster.arrive.aligned;" ::: "memory");
    asm volatile("barrier.cluster.wait.aligned;" ::: "memory");
}

// All reduced values are bit patterns of floats >= +0.0, so unsigned-int max
// on the raw bits is exactly f32 max (monotone encoding for non-negative IEEE).
__device__ __forceinline__ uint32_t redux_max_u32(uint32_t v) {
    uint32_t r;
    asm volatile("redux.sync.max.u32 %0, %1, 0xffffffff;" : "=r"(r) : "r"(v));
    return r;
}

__device__ __forceinline__ int redux_min_s32(int v) {
    int r;
    asm volatile("redux.sync.min.s32 %0, %1, 0xffffffff;" : "=r"(r) : "r"(v));
    return r;
}

__device__ __forceinline__ void mbar_wait_cluster(uint32_t addr, int parity) {
    asm volatile(
        "{\n\t"
        ".reg .pred P;\n\t"
        "LWAIT_%=:\n\t"
        "mbarrier.try_wait.parity.acquire.cluster.shared::cta.b64 P, [%0], %1, 0x989680;\n\t"
        "@!P bra LWAIT_%=;\n\t"
        "}"
        :: "r"(addr), "r"(parity) : "memory");
}

__global__ void __launch_bounds__(NTHREADS, 1) __cluster_dims__(CLUSTER, 1, 1)
fps_kernel(const float* __restrict__ xyz)
{
    extern __shared__ char smem_raw[];
    SmemLayout* sm = reinterpret_cast<SmemLayout*>(smem_raw);

    const int t    = threadIdx.x;
    const int rank = blockIdx.x & (CLUSTER - 1);
    const int b    = blockIdx.x >> 3;
    const float* xb = xyz + (size_t)b * 3 * NPTS;
    const int g0 = rank * PTS_PER_CTA + t;

    float px[PPT], py[PPT], pz[PPT], dist[PPT];
    const float INF = __int_as_float(0x7f800000);

#pragma unroll
    for (int i = 0; i < PPT; i++) {
        int g = g0 + i * NTHREADS;
        px[i] = xb[g];
        py[i] = xb[NPTS + g];
        pz[i] = xb[2 * NPTS + g];
        sm->coords[t + i * NTHREADS] = make_float4(px[i], py[i], pz[i], 0.0f);
        dist[i] = INF;
    }
    // initial winner = point 0 (every thread loads it)
    float wx = xb[0], wy = xb[NPTS], wz = xb[2 * NPTS];

    if (t == 0) {
        asm volatile("mbarrier.init.shared.b64 [%0], %1;"
                     :: "r"(smem_u32(&sm->full[0])), "r"((uint32_t)CLUSTER) : "memory");
        asm volatile("mbarrier.init.shared.b64 [%0], %1;"
                     :: "r"(smem_u32(&sm->full[1])), "r"((uint32_t)CLUSTER) : "memory");
        if (rank == 0) g_idx[b * NK] = 0;
    }
    __syncthreads();
    cluster_barrier();   // mbarriers + coords visible cluster-wide

    const int wid = t >> 5, lane = t & 31;
    uint32_t cand_mine[2], full_addr[2];
    cand_mine[0] = smem_u32(&sm->cand[0][rank][0]);
    cand_mine[1] = smem_u32(&sm->cand[1][rank][0]);
    full_addr[0] = smem_u32(&sm->full[0]);
    full_addr[1] = smem_u32(&sm->full[1]);
    int ph0 = 0, ph1 = 0;

    for (int k = 1; k < NK; k++) {
        const int buf = k & 1;

        // ---- distance update (bit-identical to the proven-correct form) ----
#pragma unroll
        for (int i = 0; i < PPT; i++) {
            float dx = px[i] - wx, dy = py[i] - wy, dz = pz[i] - wz;
            float d  = fmaf(dz, dz, fmaf(dy, dy, dx * dx));
            dist[i]  = fminf(dist[i], d);
        }
        // ---- best-of-4 tree, first-index tiebreak (i0 < i1 < i2 < i3) ----
        float m01 = fmaxf(dist[0], dist[1]);
        int   i01 = (dist[0] >= dist[1]) ? g0 : g0 + NTHREADS;
        float m23 = fmaxf(dist[2], dist[3]);
        int   i23 = (dist[2] >= dist[3]) ? g0 + 2 * NTHREADS : g0 + 3 * NTHREADS;
        float bestv = fmaxf(m01, m23);
        int   besti = (m01 >= m23) ? i01 : i23;

        // ---- warp argmax via integer redux (exact min-index tiebreak) ----
        uint32_t bvb  = __float_as_uint(bestv);   // >= +0.0 -> u32-monotone
        uint32_t wmax = redux_max_u32(bvb);
        int      cidx = (bvb == wmax) ? besti : 0x7fffffff;
        int      wmin = redux_min_s32(cidx);
        if (lane == 0) sm->warp_vi[wid] = make_uint2(wmax, (uint32_t)wmin);

        // intra-CTA barrier: only warp 0 blocks, others arrive and go sleep on mbarrier
        if (wid == 0) {
            asm volatile("bar.sync 1, %0;" :: "r"(NTHREADS) : "memory");
            // ---- block argmax over 32 warp candidates ----
            uint2    wc = sm->warp_vi[lane];
            uint32_t vb = wc.x;
            int      id = (int)wc.y;
            uint32_t mv = redux_max_u32(vb);
            int      cc = (vb == mv) ? id : 0x7fffffff;
            int      mi = redux_min_s32(cc);
            if (lane == 0) {
                float4 cd = sm->coords[mi - rank * PTS_PER_CTA];
                uint32_t xb_ = __float_as_uint(cd.x);
                uint32_t yb  = __float_as_uint(cd.y);
                uint32_t zb  = __float_as_uint(cd.z);
                uint32_t la  = cand_mine[buf];
#pragma unroll
                for (int r = 0; r < CLUSTER; r++) {
                    uint32_t ra = mapa_rank(la, (uint32_t)r);
                    asm volatile("st.shared::cluster.v4.b32 [%0], {%1,%2,%3,%4};"
                                 :: "r"(ra), "r"(mv), "r"((uint32_t)mi), "r"(xb_), "r"(yb)
                                 : "memory");
                    asm volatile("st.shared::cluster.b32 [%0], %1;"
                                 :: "r"(ra + 16), "r"(zb) : "memory");
                }
#pragma unroll
                for (int r = 0; r < CLUSTER; r++) {
                    uint32_t fa = mapa_rank(full_addr[buf], (uint32_t)r);
                    asm volatile("mbarrier.arrive.release.cluster.shared::cluster.b64 _, [%0];"
                                 :: "r"(fa) : "memory");
                }
            }
        } else {
            asm volatile("bar.arrive 1, %0;" :: "r"(NTHREADS) : "memory");
        }

        // ---- wait for all 8 CTAs' candidates ----
        mbar_wait_cluster(full_addr[buf], buf ? ph1 : ph0);
        if (buf) ph1 ^= 1; else ph0 ^= 1;

        // ---- every warp resolves the cluster winner itself (no block sync) ----
        uint32_t vb = 0u;              // +0.0: can tie but never beat a real candidate
        int      id = 0x7fffffff;
        float cx = 0.f, cy = 0.f, cz = 0.f;
        if (lane < CLUSTER) {
            const uint4 r4 = *reinterpret_cast<const uint4*>(&sm->cand[buf][lane][0]);
            vb = r4.x;
            id = (int)r4.y;
            cx = __uint_as_float(r4.z);
            cy = __uint_as_float(r4.w);
            cz = __uint_as_float(sm->cand[buf][lane][4]);
        }
        uint32_t mv = redux_max_u32(vb);
        int      cc = (vb == mv) ? id : 0x7fffffff;
        int      mi = redux_min_s32(cc);
        unsigned msk = __ballot_sync(0xffffffffu, (vb == mv) && (id == mi));
        int src = __ffs(msk) - 1;
        wx = __shfl_sync(0xffffffffu, cx, src);
        wy = __shfl_sync(0xffffffffu, cy, src);
        wz = __shfl_sync(0xffffffffu, cz, src);

        if (rank == 0 && t == 0) g_idx[b * NK + k] = mi;
    }
}

// out = [node_static (8,3,1024) | node_feature (8,128,1024)]
__global__ void __launch_bounds__(NK) gather_kernel(
    const float* __restrict__ xyz,
    const float* __restrict__ feat,
    float* __restrict__ out)
{
    int k = threadIdx.x;
    int c = blockIdx.x;     // 0..130: 0-2 -> xyz planes, 3..130 -> feature planes
    int b = blockIdx.y;
    int idx = g_idx[b * NK + k];
    if (c < 3) {
        out[(size_t)b * 3 * NK + (size_t)c * NK + k] =
            xyz[(size_t)b * 3 * NPTS + (size_t)c * NPTS + idx];
    } else {
        int cf = c - 3;
        out[(size_t)NB * 3 * NK + (size_t)b * NC * NK + (size_t)cf * NK + k] =
            feat[(size_t)b * NC * NPTS + (size_t)cf * NPTS + idx];
    }
}

extern "C" void kernel_launch(void* const* d_in, const int* in_sizes, int n_in,
                              void* d_out, int out_size)
{
    const float* xyz  = (const float*)d_in[0];
    const float* feat = (const float*)d_in[1];
    float* out = (float*)d_out;

    size_t smem = sizeof(SmemLayout);
    cudaFuncSetAttribute(fps_kernel, cudaFuncAttributeMaxDynamicSharedMemorySize, (int)smem);

    fps_kernel<<<NB * CLUSTER, NTHREADS, smem>>>(xyz);
    gather_kernel<<<dim3(NC + 3, NB), NK>>>(xyz, feat, out);
}

// round 5
// speedup vs baseline: 2.3513x; 2.3513x over previous
#include <cuda_runtime.h>
#include <cstdint>

#define NB 8
#define NPTS 32768
#define NC 128
#define NK 1024
#define CLUSTER 8
#define PTS_PER_CTA (NPTS / CLUSTER)     // 4096
#define NTHREADS 1024
#define PPT (PTS_PER_CTA / NTHREADS)     // 4

// sampled indices scratch (device global: no allocation allowed)
__device__ int g_idx[NB * NK];

struct SmemLayout {
    float4   coords[PTS_PER_CTA];      // 64 KB — winner coord lookup
    uint2    warp_vi[32];              // per-warp (valbits, idx)
    uint32_t cand[2][CLUSTER][8];      // double-buffered 32B candidate slots
};

__device__ __forceinline__ uint32_t smem_u32(const void* p) {
    uint32_t a;
    asm("{ .reg .u64 t; cvta.to.shared.u64 t, %1; cvt.u32.u64 %0, t; }"
        : "=r"(a) : "l"(p));
    return a;
}

__device__ __forceinline__ uint32_t mapa_rank(uint32_t laddr, uint32_t rank) {
    uint32_t r;
    asm("mapa.shared::cluster.u32 %0, %1, %2;" : "=r"(r) : "r"(laddr), "r"(rank));
    return r;
}

__device__ __forceinline__ void cluster_arrive() {
    asm volatile("barrier.cluster.arrive.aligned;" ::: "memory");
}
__device__ __forceinline__ void cluster_wait() {
    asm volatile("barrier.cluster.wait.aligned;" ::: "memory");
}

// All reduced values are bit patterns of floats >= +0.0, so unsigned-int max
// on the raw bits is exactly f32 max (monotone encoding for non-negative IEEE).
__device__ __forceinline__ uint32_t redux_max_u32(uint32_t v) {
    uint32_t r;
    asm volatile("redux.sync.max.u32 %0, %1, 0xffffffff;" : "=r"(r) : "r"(v));
    return r;
}

__device__ __forceinline__ int redux_min_s32(int v) {
    int r;
    asm volatile("redux.sync.min.s32 %0, %1, 0xffffffff;" : "=r"(r) : "r"(v));
    return r;
}

__global__ void __launch_bounds__(NTHREADS, 1) __cluster_dims__(CLUSTER, 1, 1)
fps_kernel(const float* __restrict__ xyz)
{
    extern __shared__ char smem_raw[];
    SmemLayout* sm = reinterpret_cast<SmemLayout*>(smem_raw);

    const int t    = threadIdx.x;
    const int rank = blockIdx.x & (CLUSTER - 1);
    const int b    = blockIdx.x >> 3;
    const float* xb = xyz + (size_t)b * 3 * NPTS;
    const int g0 = rank * PTS_PER_CTA + t;

    float px[PPT], py[PPT], pz[PPT], dist[PPT];
    const float INF = __int_as_float(0x7f800000);

#pragma unroll
    for (int i = 0; i < PPT; i++) {
        int g = g0 + i * NTHREADS;
        px[i] = xb[g];
        py[i] = xb[NPTS + g];
        pz[i] = xb[2 * NPTS + g];
        sm->coords[t + i * NTHREADS] = make_float4(px[i], py[i], pz[i], 0.0f);
        dist[i] = INF;
    }
    // initial winner = point 0 (every thread loads it)
    float wx = xb[0], wy = xb[NPTS], wz = xb[2 * NPTS];
    if (rank == 0 && t == 0) g_idx[b * NK] = 0;

    const int wid = t >> 5, lane = t & 31;
    uint32_t cand_mine[2];
    cand_mine[0] = smem_u32(&sm->cand[0][rank][0]);
    cand_mine[1] = smem_u32(&sm->cand[1][rank][0]);

    __syncthreads();
    cluster_arrive();
    cluster_wait();

    for (int k = 1; k < NK; k++) {
        const int buf = k & 1;

        // ---- distance update (bit-identical to the proven-correct form) ----
#pragma unroll
        for (int i = 0; i < PPT; i++) {
            float dx = px[i] - wx, dy = py[i] - wy, dz = pz[i] - wz;
            float d  = fmaf(dz, dz, fmaf(dy, dy, dx * dx));
            dist[i]  = fminf(dist[i], d);
        }
        // ---- best-of-4 tree, first-index tiebreak (i0 < i1 < i2 < i3) ----
        float m01 = fmaxf(dist[0], dist[1]);
        int   i01 = (dist[0] >= dist[1]) ? g0 : g0 + NTHREADS;
        float m23 = fmaxf(dist[2], dist[3]);
        int   i23 = (dist[2] >= dist[3]) ? g0 + 2 * NTHREADS : g0 + 3 * NTHREADS;
        float bestv = fmaxf(m01, m23);
        int   besti = (m01 >= m23) ? i01 : i23;

        // ---- warp argmax via integer redux (exact min-index tiebreak) ----
        uint32_t bvb  = __float_as_uint(bestv);   // >= +0.0 -> u32-monotone
        uint32_t wmax = redux_max_u32(bvb);
        int      cidx = (bvb == wmax) ? besti : 0x7fffffff;
        int      wmin = redux_min_s32(cidx);
        if (lane == 0) sm->warp_vi[wid] = make_uint2(wmax, (uint32_t)wmin);

        if (wid == 0) {
            // warp0 consumes the 32 warp candidates once all have stored them
            asm volatile("bar.sync 1, %0;" :: "r"(NTHREADS) : "memory");
            uint2    wc = sm->warp_vi[lane];
            uint32_t vb = wc.x;
            int      id = (int)wc.y;
            uint32_t mv = redux_max_u32(vb);
            int      cc = (vb == mv) ? id : 0x7fffffff;
            int      mi = redux_min_s32(cc);
            // lanes 0-7 broadcast the CTA candidate to peer CTAs in parallel
            float4 cd = sm->coords[mi - rank * PTS_PER_CTA];  // broadcast LDS
            if (lane < CLUSTER) {
                uint32_t ra = mapa_rank(cand_mine[buf], (uint32_t)lane);
                asm volatile("st.shared::cluster.v4.b32 [%0], {%1,%2,%3,%4};"
                             :: "r"(ra), "r"(mv), "r"((uint32_t)mi),
                                "r"(__float_as_uint(cd.x)), "r"(__float_as_uint(cd.y))
                             : "memory");
                asm volatile("st.shared::cluster.b32 [%0], %1;"
                             :: "r"(ra + 16), "r"(__float_as_uint(cd.z)) : "memory");
            }
            cluster_arrive();   // release: orders the candidate stores
        } else {
            asm volatile("bar.arrive 1, %0;" :: "r"(NTHREADS) : "memory");
            cluster_arrive();   // arrive early; hide skew behind warp0's work
        }
        cluster_wait();         // acquire: all 8 candidates visible

        // ---- every warp resolves the cluster winner itself (no block sync) ----
        uint32_t vb = 0u;              // +0.0: can tie but never beat a real candidate
        int      id = 0x7fffffff;
        float cx = 0.f, cy = 0.f, cz = 0.f;
        if (lane < CLUSTER) {
            const uint4 r4 = *reinterpret_cast<const uint4*>(&sm->cand[buf][lane][0]);
            vb = r4.x;
            id = (int)r4.y;
            cx = __uint_as_float(r4.z);
            cy = __uint_as_float(r4.w);
            cz = __uint_as_float(sm->cand[buf][lane][4]);
        }
        uint32_t mv = redux_max_u32(vb);
        int      cc = (vb == mv) ? id : 0x7fffffff;
        int      mi = redux_min_s32(cc);
        unsigned msk = __ballot_sync(0xffffffffu, (vb == mv) && (id == mi));
        int src = __ffs(msk) - 1;
        wx = __shfl_sync(0xffffffffu, cx, src);
        wy = __shfl_sync(0xffffffffu, cy, src);
        wz = __shfl_sync(0xffffffffu, cz, src);

        if (rank == 0 && t == 0) g_idx[b * NK + k] = mi;
    }
}

// out = [node_static (8,3,1024) | node_feature (8,128,1024)]
__global__ void __launch_bounds__(NK) gather_kernel(
    const float* __restrict__ xyz,
    const float* __restrict__ feat,
    float* __restrict__ out)
{
    int k = threadIdx.x;
    int c = blockIdx.x;     // 0..130: 0-2 -> xyz planes, 3..130 -> feature planes
    int b = blockIdx.y;
    int idx = g_idx[b * NK + k];
    if (c < 3) {
        out[(size_t)b * 3 * NK + (size_t)c * NK + k] =
            xyz[(size_t)b * 3 * NPTS + (size_t)c * NPTS + idx];
    } else {
        int cf = c - 3;
        out[(size_t)NB * 3 * NK + (size_t)b * NC * NK + (size_t)cf * NK + k] =
            feat[(size_t)b * NC * NPTS + (size_t)cf * NPTS + idx];
    }
}

extern "C" void kernel_launch(void* const* d_in, const int* in_sizes, int n_in,
                              void* d_out, int out_size)
{
    const float* xyz  = (const float*)d_in[0];
    const float* feat = (const float*)d_in[1];
    float* out = (float*)d_out;

    size_t smem = sizeof(SmemLayout);
    cudaFuncSetAttribute(fps_kernel, cudaFuncAttributeMaxDynamicSharedMemorySize, (int)smem);

    fps_kernel<<<NB * CLUSTER, NTHREADS, smem>>>(xyz);
    gather_kernel<<<dim3(NC + 3, NB), NK>>>(xyz, feat, out);
}

// round 6
// speedup vs baseline: 2.4113x; 1.0255x over previous
#include <cuda_runtime.h>
#include <cstdint>

#define NB 8
#define NPTS 32768
#define NC 128
#define NK 1024
#define CLUSTER 8
#define PTS_PER_CTA (NPTS / CLUSTER)     // 4096
#define NTHREADS 1024
#define PPT (PTS_PER_CTA / NTHREADS)     // 4
#define NPAIR (PPT / 2)                  // 2

// sampled indices scratch (device global: no allocation allowed)
__device__ int g_idx[NB * NK];

struct SmemLayout {
    float4   coords[PTS_PER_CTA];      // 64 KB — winner coord lookup
    uint2    warp_vi[32];              // per-warp (valbits, idx)
    uint32_t cand[2][CLUSTER][8];      // double-buffered 32B candidate slots
};

__device__ __forceinline__ uint32_t smem_u32(const void* p) {
    uint32_t a;
    asm("{ .reg .u64 t; cvta.to.shared.u64 t, %1; cvt.u32.u64 %0, t; }"
        : "=r"(a) : "l"(p));
    return a;
}

__device__ __forceinline__ uint32_t mapa_rank(uint32_t laddr, uint32_t rank) {
    uint32_t r;
    asm("mapa.shared::cluster.u32 %0, %1, %2;" : "=r"(r) : "r"(laddr), "r"(rank));
    return r;
}

__device__ __forceinline__ void cluster_arrive() {
    asm volatile("barrier.cluster.arrive.aligned;" ::: "memory");
}
__device__ __forceinline__ void cluster_wait() {
    asm volatile("barrier.cluster.wait.aligned;" ::: "memory");
}

// All reduced values are bit patterns of floats >= +0.0, so unsigned-int max
// on the raw bits is exactly f32 max (monotone encoding for non-negative IEEE).
__device__ __forceinline__ uint32_t redux_max_u32(uint32_t v) {
    uint32_t r;
    asm volatile("redux.sync.max.u32 %0, %1, 0xffffffff;" : "=r"(r) : "r"(v));
    return r;
}

__device__ __forceinline__ int redux_min_s32(int v) {
    int r;
    asm volatile("redux.sync.min.s32 %0, %1, 0xffffffff;" : "=r"(r) : "r"(v));
    return r;
}

// ---- packed f32x2 helpers (two independent rn fp32 lanes, bit-identical) ----
__device__ __forceinline__ uint64_t pack2(float lo, float hi) {
    uint64_t r;
    asm("mov.b64 %0, {%1, %2};" : "=l"(r) : "f"(lo), "f"(hi));
    return r;
}
__device__ __forceinline__ void unpack2(uint64_t v, uint32_t& lo, uint32_t& hi) {
    asm("mov.b64 {%0, %1}, %2;" : "=r"(lo), "=r"(hi) : "l"(v));
}
__device__ __forceinline__ uint64_t add2(uint64_t a, uint64_t b) {
    uint64_t r;
    asm("add.rn.f32x2 %0, %1, %2;" : "=l"(r) : "l"(a), "l"(b));
    return r;
}
__device__ __forceinline__ uint64_t mul2(uint64_t a, uint64_t b) {
    uint64_t r;
    asm("mul.rn.f32x2 %0, %1, %2;" : "=l"(r) : "l"(a), "l"(b));
    return r;
}
__device__ __forceinline__ uint64_t fma2(uint64_t a, uint64_t b, uint64_t c) {
    uint64_t r;
    asm("fma.rn.f32x2 %0, %1, %2, %3;" : "=l"(r) : "l"(a), "l"(b), "l"(c));
    return r;
}

__global__ void __launch_bounds__(NTHREADS, 1) __cluster_dims__(CLUSTER, 1, 1)
fps_kernel(const float* __restrict__ xyz)
{
    extern __shared__ char smem_raw[];
    SmemLayout* sm = reinterpret_cast<SmemLayout*>(smem_raw);

    const int t    = threadIdx.x;
    const int rank = blockIdx.x & (CLUSTER - 1);
    const int b    = blockIdx.x >> 3;
    const float* xb = xyz + (size_t)b * 3 * NPTS;
    const int g0 = rank * PTS_PER_CTA + t;

    // pair j holds points i=2j (lo lane) and i=2j+1 (hi lane); point i ↔ global
    // index g0 + i*NTHREADS (ascending in i, preserving first-index tiebreak)
    uint64_t pxp[NPAIR], pyp[NPAIR], pzp[NPAIR];
    uint32_t db[PPT];                  // dist as raw bits (>= +0.0, u32-monotone)
    const uint32_t INF_BITS = 0x7f800000u;

#pragma unroll
    for (int j = 0; j < NPAIR; j++) {
        int gl = g0 + (2 * j) * NTHREADS;
        int gh = g0 + (2 * j + 1) * NTHREADS;
        float xl = xb[gl],            xh = xb[gh];
        float yl = xb[NPTS + gl],     yh = xb[NPTS + gh];
        float zl = xb[2 * NPTS + gl], zh = xb[2 * NPTS + gh];
        pxp[j] = pack2(xl, xh);
        pyp[j] = pack2(yl, yh);
        pzp[j] = pack2(zl, zh);
        sm->coords[t + (2 * j) * NTHREADS]     = make_float4(xl, yl, zl, 0.0f);
        sm->coords[t + (2 * j + 1) * NTHREADS] = make_float4(xh, yh, zh, 0.0f);
        db[2 * j] = INF_BITS;
        db[2 * j + 1] = INF_BITS;
    }
    // initial winner = point 0 (every thread loads it)
    float wx = xb[0], wy = xb[NPTS], wz = xb[2 * NPTS];
    if (rank == 0 && t == 0) g_idx[b * NK] = 0;

    const int wid = t >> 5, lane = t & 31;
    uint32_t cand_mine[2];
    cand_mine[0] = smem_u32(&sm->cand[0][rank][0]);
    cand_mine[1] = smem_u32(&sm->cand[1][rank][0]);

    __syncthreads();
    cluster_arrive();
    cluster_wait();

    for (int k = 1; k < NK; k++) {
        const int buf = k & 1;

        // ---- distance update, packed (p - w == p + (-w), bit-exact) ----
        float nwx = -wx, nwy = -wy, nwz = -wz;
        uint64_t nwx2 = pack2(nwx, nwx);
        uint64_t nwy2 = pack2(nwy, nwy);
        uint64_t nwz2 = pack2(nwz, nwz);
#pragma unroll
        for (int j = 0; j < NPAIR; j++) {
            uint64_t dx = add2(pxp[j], nwx2);
            uint64_t dy = add2(pyp[j], nwy2);
            uint64_t dz = add2(pzp[j], nwz2);
            uint64_t s  = mul2(dx, dx);
            s = fma2(dy, dy, s);
            s = fma2(dz, dz, s);          // lane-wise == fmaf(dz,dz,fmaf(dy,dy,dx*dx))
            uint32_t d0, d1;
            unpack2(s, d0, d1);
            db[2 * j]     = umin(db[2 * j], d0);       // IMNMX.U32 (alu pipe)
            db[2 * j + 1] = umin(db[2 * j + 1], d1);
        }
        // ---- best-of-4 tree on bits, first-index tiebreak (alu pipe) ----
        uint32_t m01 = umax(db[0], db[1]);
        int      i01 = (db[0] >= db[1]) ? g0 : g0 + NTHREADS;
        uint32_t m23 = umax(db[2], db[3]);
        int      i23 = (db[2] >= db[3]) ? g0 + 2 * NTHREADS : g0 + 3 * NTHREADS;
        uint32_t bvb   = umax(m01, m23);
        int      besti = (m01 >= m23) ? i01 : i23;

        // ---- warp argmax via integer redux (exact min-index tiebreak) ----
        uint32_t wmax = redux_max_u32(bvb);
        int      cidx = (bvb == wmax) ? besti : 0x7fffffff;
        int      wmin = redux_min_s32(cidx);
        if (lane == 0) sm->warp_vi[wid] = make_uint2(wmax, (uint32_t)wmin);

        if (wid == 0) {
            // warp0 consumes the 32 warp candidates once all have stored them
            asm volatile("bar.sync 1, %0;" :: "r"(NTHREADS) : "memory");
            uint2    wc = sm->warp_vi[lane];
            uint32_t vb = wc.x;
            int      id = (int)wc.y;
            uint32_t mv = redux_max_u32(vb);
            int      cc = (vb == mv) ? id : 0x7fffffff;
            int      mi = redux_min_s32(cc);
            // lanes 0-7 broadcast the CTA candidate to peer CTAs in parallel
            float4 cd = sm->coords[mi - rank * PTS_PER_CTA];  // broadcast LDS
            if (lane < CLUSTER) {
                uint32_t ra = mapa_rank(cand_mine[buf], (uint32_t)lane);
                asm volatile("st.shared::cluster.v4.b32 [%0], {%1,%2,%3,%4};"
                             :: "r"(ra), "r"(mv), "r"((uint32_t)mi),
                                "r"(__float_as_uint(cd.x)), "r"(__float_as_uint(cd.y))
                             : "memory");
                asm volatile("st.shared::cluster.b32 [%0], %1;"
                             :: "r"(ra + 16), "r"(__float_as_uint(cd.z)) : "memory");
            }
            cluster_arrive();   // release: orders the candidate stores
        } else {
            asm volatile("bar.arrive 1, %0;" :: "r"(NTHREADS) : "memory");
            cluster_arrive();   // arrive early; hide skew behind warp0's work
        }
        cluster_wait();         // acquire: all 8 candidates visible

        // ---- every warp resolves the cluster winner itself (no block sync) ----
        uint32_t vb = 0u;              // +0.0: can tie but never beat a real candidate
        int      id = 0x7fffffff;
        float cx = 0.f, cy = 0.f, cz = 0.f;
        if (lane < CLUSTER) {
            const uint4 r4 = *reinterpret_cast<const uint4*>(&sm->cand[buf][lane][0]);
            vb = r4.x;
            id = (int)r4.y;
            cx = __uint_as_float(r4.z);
            cy = __uint_as_float(r4.w);
            cz = __uint_as_float(sm->cand[buf][lane][4]);
        }
        uint32_t mv = redux_max_u32(vb);
        int      cc = (vb == mv) ? id : 0x7fffffff;
        int      mi = redux_min_s32(cc);
        unsigned msk = __ballot_sync(0xffffffffu, (vb == mv) && (id == mi));
        int src = __ffs(msk) - 1;
        wx = __shfl_sync(0xffffffffu, cx, src);
        wy = __shfl_sync(0xffffffffu, cy, src);
        wz = __shfl_sync(0xffffffffu, cz, src);

        if (rank == 0 && t == 0) g_idx[b * NK + k] = mi;
    }
}

// out = [node_static (8,3,1024) | node_feature (8,128,1024)]
__global__ void __launch_bounds__(NK) gather_kernel(
    const float* __restrict__ xyz,
    const float* __restrict__ feat,
    float* __restrict__ out)
{
    int k = threadIdx.x;
    int c = blockIdx.x;     // 0..130: 0-2 -> xyz planes, 3..130 -> feature planes
    int b = blockIdx.y;
    int idx = g_idx[b * NK + k];
    if (c < 3) {
        out[(size_t)b * 3 * NK + (size_t)c * NK + k] =
            xyz[(size_t)b * 3 * NPTS + (size_t)c * NPTS + idx];
    } else {
        int cf = c - 3;
        out[(size_t)NB * 3 * NK + (size_t)b * NC * NK + (size_t)cf * NK + k] =
            feat[(size_t)b * NC * NPTS + (size_t)cf * NPTS + idx];
    }
}

extern "C" void kernel_launch(void* const* d_in, const int* in_sizes, int n_in,
                              void* d_out, int out_size)
{
    const float* xyz  = (const float*)d_in[0];
    const float* feat = (const float*)d_in[1];
    float* out = (float*)d_out;

    size_t smem = sizeof(SmemLayout);
    cudaFuncSetAttribute(fps_kernel, cudaFuncAttributeMaxDynamicSharedMemorySize, (int)smem);

    fps_kernel<<<NB * CLUSTER, NTHREADS, smem>>>(xyz);
    gather_kernel<<<dim3(NC + 3, NB), NK>>>(xyz, feat, out);
}